// round 10
// baseline (speedup 1.0000x reference)
#include <cuda_runtime.h>
#include <math.h>

#define DD   64
#define NUU  100000
#define NII  50000
#define NNODE 150000
#define BB   16384
#define CFD  256
#define EE   2000000
#define ETOT (EE + NNODE)           // 2,150,000 (edges + self loops)
#define NBLK 147                    // ceil(NNODE/1024)
#define ACTBIT 0x40000000
#define SRCMASK 0x3FFFFFFF

// ---------------- scratch (device globals; no runtime allocation) ----------------
__device__ __align__(16) float g_x[(size_t)NNODE * 128];    // layer-1 input; reused as h1
__device__ __align__(16) float g_xw1[(size_t)NNODE * 128];  // x @ W1 (only active rows valid)
__device__ __align__(16) float g_xw2[(size_t)NNODE * 64];   // h1 @ W2
__device__ __align__(16) float g_out2[(size_t)NNODE * 64];  // layer-2 output (active dst rows)
__device__ __align__(16) float g_cemb[(size_t)BB * 64];     // content projection
__device__ __align__(16) float g_als1[NNODE * 2];
__device__ __align__(16) float g_ald1[NNODE * 2];
__device__ __align__(16) float g_als2[NNODE];
__device__ __align__(16) float g_ald2[NNODE];
__device__ __align__(16) unsigned char g_active[NNODE];
__device__ __align__(16) int   g_cnt[NNODE];
__device__ __align__(16) int   g_rowptr[NNODE + 1];
__device__ __align__(16) int   g_woff[NNODE];
__device__ __align__(16) int   g_srcs[ETOT];
__device__ __align__(16) int   g_bsum[256];
__device__ __align__(16) int   g_bsumx[256];

// ---------------- helpers ----------------
__device__ __forceinline__ float warpSumAll(float v) {
#pragma unroll
    for (int o = 16; o > 0; o >>= 1) v += __shfl_xor_sync(0xffffffffu, v, o);
    return v;
}
__device__ __forceinline__ float lrelu02(float x) { return x > 0.f ? x : 0.2f * x; }

// ---------------- init: zero logit arrays + active flags, cnt=1 (self loop) ----------------
__global__ void k_init() {
    size_t tid = (size_t)blockIdx.x * blockDim.x + threadIdx.x;
    size_t stride = (size_t)gridDim.x * blockDim.x;
    float4 z = make_float4(0.f, 0.f, 0.f, 0.f);
    float4* pa = reinterpret_cast<float4*>(g_als1);
    float4* pb = reinterpret_cast<float4*>(g_ald1);
    for (size_t i = tid; i < (size_t)NNODE * 2 / 4; i += stride) { pa[i] = z; pb[i] = z; }
    for (size_t i = tid; i < NNODE; i += stride) { g_cnt[i] = 1; g_active[i] = 0; }
}

// ---------------- generic M x 64 GEMM (out = A @ W [+ bias]) ----------------
// MODE 0: cemb = content @ cp_w + cp_b   (A = param, out = g_cemb)
// MODE 1: xw2  = g_x(h1) @ w2            (out = g_xw2)
template <int KDIM, int M, int LDA, int MODE>
__global__ void k_gemm64(const float* __restrict__ Aparam,
                         const float* __restrict__ W,
                         const float* __restrict__ bias) {
    __shared__ float As[16][128];
    __shared__ float Bs[16][64];
    const float* A = (MODE == 1) ? g_x : Aparam;
    float* out = (MODE == 1) ? g_xw2 : g_cemb;

    int t = threadIdx.x;                 // 256 threads
    int rbase = blockIdx.x * 128;
    int ct = t & 15;                     // 16 col-threads * 4 cols = 64
    int rt = t >> 4;                     // 16 row-threads * 8 rows = 128
    float acc[8][4];
#pragma unroll
    for (int i = 0; i < 8; i++)
#pragma unroll
        for (int j = 0; j < 4; j++) acc[i][j] = 0.f;

    for (int kb = 0; kb < KDIM; kb += 16) {
#pragma unroll
        for (int rep = 0; rep < 2; rep++) {
            int idx = t + 256 * rep;     // 512 float4
            int row = idx >> 2, kq = idx & 3;
            int r = rbase + row;
            float4 v = make_float4(0.f, 0.f, 0.f, 0.f);
            if (r < M) v = *reinterpret_cast<const float4*>(&A[(size_t)r * LDA + kb + kq * 4]);
            As[kq * 4 + 0][row] = v.x;
            As[kq * 4 + 1][row] = v.y;
            As[kq * 4 + 2][row] = v.z;
            As[kq * 4 + 3][row] = v.w;
        }
        {
            int kk = t >> 4, col = (t & 15) * 4;
            *reinterpret_cast<float4*>(&Bs[kk][col]) =
                *reinterpret_cast<const float4*>(&W[(size_t)(kb + kk) * 64 + col]);
        }
        __syncthreads();
#pragma unroll
        for (int k = 0; k < 16; k++) {
            float a[8];
            *reinterpret_cast<float4*>(&a[0]) = *reinterpret_cast<float4*>(&As[k][rt * 8]);
            *reinterpret_cast<float4*>(&a[4]) = *reinterpret_cast<float4*>(&As[k][rt * 8 + 4]);
            float4 b = *reinterpret_cast<float4*>(&Bs[k][ct * 4]);
#pragma unroll
            for (int i = 0; i < 8; i++) {
                acc[i][0] += a[i] * b.x;
                acc[i][1] += a[i] * b.y;
                acc[i][2] += a[i] * b.z;
                acc[i][3] += a[i] * b.w;
            }
        }
        __syncthreads();
    }
#pragma unroll
    for (int i = 0; i < 8; i++) {
        int r = rbase + rt * 8 + i;
        if (r < M) {
            float4 v = make_float4(acc[i][0], acc[i][1], acc[i][2], acc[i][3]);
            if (bias) {
                v.x += bias[ct * 4 + 0];
                v.y += bias[ct * 4 + 1];
                v.z += bias[ct * 4 + 2];
                v.w += bias[ct * 4 + 3];
            }
            *reinterpret_cast<float4*>(&out[(size_t)r * 64 + ct * 4]) = v;
        }
    }
}

// ---------------- scatter embeddings into node features (+ active flags) ----------------
__global__ void k_scatter(const int* __restrict__ uids, const int* __restrict__ iids,
                          const float* __restrict__ uemb, const float* __restrict__ iemb) {
    int b = blockIdx.x;
    int j = threadIdx.x;  // 64
    int uid = uids[b];
    int iid = iids[b];
    g_x[(size_t)uid * 128 + j] = uemb[(size_t)uid * 64 + j];
    g_x[(size_t)uid * 128 + 64 + j] = 0.f;
    g_x[(size_t)(NUU + iid) * 128 + j] = iemb[(size_t)iid * 64 + j];
    g_x[(size_t)(NUU + iid) * 128 + 64 + j] = g_cemb[(size_t)b * 64 + j];
    if (j == 0) { g_active[uid] = 1; g_active[NUU + iid] = 1; }
}

// ---------------- CSR build ----------------
__global__ void k_hist(const int* __restrict__ ei) {
    int stride = gridDim.x * blockDim.x;
    for (int e = blockIdx.x * blockDim.x + threadIdx.x; e < EE; e += stride)
        atomicAdd(&g_cnt[ei[EE + e]], 1);
}

__global__ void k_scanA() {
    __shared__ int sm[1024];
    int t = threadIdx.x;
    int i = blockIdx.x * 1024 + t;
    int v = (i < NNODE) ? g_cnt[i] : 0;
    sm[t] = v;
    __syncthreads();
    for (int o = 1; o < 1024; o <<= 1) {
        int x = (t >= o) ? sm[t - o] : 0;
        __syncthreads();
        sm[t] += x;
        __syncthreads();
    }
    if (i < NNODE) g_rowptr[i] = sm[t] - v;
    if (t == 1023) g_bsum[blockIdx.x] = sm[1023];
}

__global__ void k_scanB() {
    __shared__ int sm[256];
    int t = threadIdx.x;
    int v = (t < NBLK) ? g_bsum[t] : 0;
    sm[t] = v;
    __syncthreads();
    for (int o = 1; o < 256; o <<= 1) {
        int x = (t >= o) ? sm[t - o] : 0;
        __syncthreads();
        sm[t] += x;
        __syncthreads();
    }
    g_bsumx[t] = sm[t] - v;
}

__global__ void k_scanC() {
    int t = threadIdx.x;
    int i = blockIdx.x * 1024 + t;
    if (i < NNODE) {
        int r = g_rowptr[i] + g_bsumx[blockIdx.x];
        g_rowptr[i] = r;
        g_woff[i] = r;
    }
    if (i == 0) g_rowptr[NNODE] = ETOT;
}

// fill CSR; tag each entry with src-activity in bit 30 (single atomic per edge)
__global__ void k_fill(const int* __restrict__ ei) {
    int stride = gridDim.x * blockDim.x;
    for (int i = blockIdx.x * blockDim.x + threadIdx.x; i < ETOT; i += stride) {
        int s, d;
        if (i < EE) { s = ei[i]; d = ei[EE + i]; }
        else { s = d = i - EE; }
        int pos = atomicAdd(&g_woff[d], 1);
        g_srcs[pos] = s | (g_active[s] ? ACTBIT : 0);
    }
}

// ---------------- layer-1 GEMM over the 2B active rows (gather/scatter) ----------------
__global__ void k_gemm1(const float* __restrict__ W,  // w1 [128,128]
                        const int* __restrict__ uids, const int* __restrict__ iids) {
    __shared__ float As[16][64];
    __shared__ float Bs[16][128];
    __shared__ int nodes[64];
    int t = threadIdx.x;                 // 256
    int rbase = blockIdx.x * 64;
    if (t < 64) {
        int r = rbase + t;
        nodes[t] = (r < BB) ? uids[r] : (NUU + iids[r - BB]);
    }
    __syncthreads();
    int ct = t & 31;                     // 32 col-threads * 4 cols = 128
    int rt = t >> 5;                     // 8 row-threads * 8 rows = 64
    float acc[8][4];
#pragma unroll
    for (int i = 0; i < 8; i++)
#pragma unroll
        for (int j = 0; j < 4; j++) acc[i][j] = 0.f;

    for (int kb = 0; kb < 128; kb += 16) {
        {
            int row = t >> 2, kq = t & 3;
            float4 v = *reinterpret_cast<const float4*>(
                &g_x[(size_t)nodes[row] * 128 + kb + kq * 4]);
            As[kq * 4 + 0][row] = v.x;
            As[kq * 4 + 1][row] = v.y;
            As[kq * 4 + 2][row] = v.z;
            As[kq * 4 + 3][row] = v.w;
        }
        {
            int off = t * 8;
            int kk = off >> 7, col = off & 127;
            const float4* p = reinterpret_cast<const float4*>(&W[(size_t)(kb + kk) * 128 + col]);
            *reinterpret_cast<float4*>(&Bs[kk][col]) = p[0];
            *reinterpret_cast<float4*>(&Bs[kk][col + 4]) = p[1];
        }
        __syncthreads();
#pragma unroll
        for (int k = 0; k < 16; k++) {
            float a[8];
            *reinterpret_cast<float4*>(&a[0]) = *reinterpret_cast<float4*>(&As[k][rt * 8]);
            *reinterpret_cast<float4*>(&a[4]) = *reinterpret_cast<float4*>(&As[k][rt * 8 + 4]);
            float4 b = *reinterpret_cast<float4*>(&Bs[k][ct * 4]);
#pragma unroll
            for (int i = 0; i < 8; i++) {
                acc[i][0] += a[i] * b.x;
                acc[i][1] += a[i] * b.y;
                acc[i][2] += a[i] * b.z;
                acc[i][3] += a[i] * b.w;
            }
        }
        __syncthreads();
    }
#pragma unroll
    for (int i = 0; i < 8; i++) {
        int row = rt * 8 + i;
        float4 v = make_float4(acc[i][0], acc[i][1], acc[i][2], acc[i][3]);
        *reinterpret_cast<float4*>(&g_xw1[(size_t)nodes[row] * 128 + ct * 4]) = v;
    }
}

// ---------------- attention logits: layer 1, ACTIVE nodes only ----------------
__global__ void k_al1(const float* __restrict__ asrc, const float* __restrict__ adst,
                      const int* __restrict__ uids, const int* __restrict__ iids) {
    int gt = blockIdx.x * blockDim.x + threadIdx.x;
    int r = gt >> 5, lane = gt & 31;
    if (r >= 2 * BB) return;
    int n = (r < BB) ? uids[r] : (NUU + iids[r - BB]);
    int cg = lane * 4;
    float4 v = *reinterpret_cast<const float4*>(&g_xw1[(size_t)n * 128 + cg]);
    float4 as = *reinterpret_cast<const float4*>(&asrc[cg]);
    float4 ad = *reinterpret_cast<const float4*>(&adst[cg]);
    float ps = v.x * as.x + v.y * as.y + v.z * as.z + v.w * as.w;
    float pd = v.x * ad.x + v.y * ad.y + v.z * ad.z + v.w * ad.w;
#pragma unroll
    for (int o = 8; o > 0; o >>= 1) {
        ps += __shfl_xor_sync(0xffffffffu, ps, o);
        pd += __shfl_xor_sync(0xffffffffu, pd, o);
    }
    if ((lane & 15) == 0) {
        int h = lane >> 4;
        g_als1[(size_t)n * 2 + h] = ps;
        g_ald1[(size_t)n * 2 + h] = pd;
    }
}

__global__ void k_al2(const float* __restrict__ asrc, const float* __restrict__ adst) {
    int gt = blockIdx.x * blockDim.x + threadIdx.x;
    int n = gt >> 5, lane = gt & 31;
    if (n >= NNODE) return;
    int cg = lane * 2;
    float2 v = *reinterpret_cast<const float2*>(&g_xw2[(size_t)n * 64 + cg]);
    float2 as = *reinterpret_cast<const float2*>(&asrc[cg]);
    float2 ad = *reinterpret_cast<const float2*>(&adst[cg]);
    float ps = v.x * as.x + v.y * as.y;
    float pd = v.x * ad.x + v.y * ad.y;
    ps = warpSumAll(ps);
    pd = warpSumAll(pd);
    if (lane == 0) { g_als2[n] = ps; g_ald2[n] = pd; }
}

// ---------------- layer-1 aggregation: single pass; active-only gathers AND active-only
// g_als1 loads (inactive sources have als1 == 0 -> lane-invariant exp(lrelu(ad))) ----------------
__global__ void k_agg1(const float* __restrict__ b1) {
    int gt = blockIdx.x * blockDim.x + threadIdx.x;
    int n = gt >> 5, lane = gt & 31;
    if (n >= NNODE) return;
    int beg = g_rowptr[n], end = g_rowptr[n + 1];
    float ad0 = g_ald1[(size_t)n * 2 + 0];
    float ad1 = g_ald1[(size_t)n * 2 + 1];
    float ei0 = __expf(lrelu02(ad0));   // inactive-source denominator contribution
    float ei1 = __expf(lrelu02(ad1));

    int cg = lane * 4;
    bool headHi = (lane >= 16);
    float den0 = 0.f, den1 = 0.f;
    float4 acc = make_float4(0.f, 0.f, 0.f, 0.f);

    for (int c = beg; c < end; c += 32) {
        int i = c + lane;
        bool valid = i < end;
        int sv = valid ? g_srcs[i] : 0;
        int s = sv & SRCMASK;
        bool act = valid && (sv & ACTBIT);
        float e0 = 0.f, e1 = 0.f;
        if (act) {   // only active sources need the random g_als1 load
            float2 as = *reinterpret_cast<const float2*>(&g_als1[(size_t)s * 2]);
            e0 = __expf(lrelu02(as.x + ad0));
            e1 = __expf(lrelu02(as.y + ad1));
        } else if (valid) {
            e0 = ei0;
            e1 = ei1;
        }
        den0 += e0;
        den1 += e1;
        unsigned amask = __ballot_sync(0xffffffffu, act);
        while (amask) {
            int j = __ffs(amask) - 1;
            amask &= amask - 1;
            int sj = __shfl_sync(0xffffffffu, s, j);
            float wa = __shfl_sync(0xffffffffu, e0, j);
            float wb = __shfl_sync(0xffffffffu, e1, j);
            float wj = headHi ? wb : wa;
            float4 xv = *reinterpret_cast<const float4*>(&g_xw1[(size_t)sj * 128 + cg]);
            acc.x += wj * xv.x;
            acc.y += wj * xv.y;
            acc.z += wj * xv.z;
            acc.w += wj * xv.w;
        }
    }
    den0 = warpSumAll(den0);
    den1 = warpSumAll(den1);
    float inv = 1.f / ((headHi ? den1 : den0) + 1e-16f);

    float4 bv = *reinterpret_cast<const float4*>(&b1[cg]);
    float4 o;
    o.x = acc.x * inv + bv.x; o.x = o.x > 0.f ? o.x : expm1f(o.x);
    o.y = acc.y * inv + bv.y; o.y = o.y > 0.f ? o.y : expm1f(o.y);
    o.z = acc.z * inv + bv.z; o.z = o.z > 0.f ? o.z : expm1f(o.z);
    o.w = acc.w * inv + bv.w; o.w = o.w > 0.f ? o.w : expm1f(o.w);
    *reinterpret_cast<float4*>(&g_x[(size_t)n * 128 + cg]) = o;  // h1 into g_x
}

// ---------------- layer-2 aggregation: ONLY over the 2B destination nodes the head reads ----------------
__global__ void k_agg2(const float* __restrict__ b2,
                       const int* __restrict__ uids, const int* __restrict__ iids) {
    int gt = blockIdx.x * blockDim.x + threadIdx.x;
    int r = gt >> 5, lane = gt & 31;
    if (r >= 2 * BB) return;
    int n = (r < BB) ? uids[r] : (NUU + iids[r - BB]);
    int beg = g_rowptr[n], end = g_rowptr[n + 1];
    float ad = g_ald2[n];

    int cg = lane * 2;
    float den = 0.f;
    float2 acc = make_float2(0.f, 0.f);
    for (int c = beg; c < end; c += 32) {
        int i = c + lane;
        bool valid = i < end;
        int s = (valid ? g_srcs[i] : 0) & SRCMASK;
        float e = valid ? __expf(lrelu02(g_als2[s] + ad)) : 0.f;
        den += e;
        int cnt = min(32, end - c);
        for (int j = 0; j < cnt; j++) {
            int sj = __shfl_sync(0xffffffffu, s, j);
            float wj = __shfl_sync(0xffffffffu, e, j);
            float2 xv = *reinterpret_cast<const float2*>(&g_xw2[(size_t)sj * 64 + cg]);
            acc.x += wj * xv.x;
            acc.y += wj * xv.y;
        }
    }
    den = warpSumAll(den);
    float inv = 1.f / (den + 1e-16f);
    float2 o = make_float2(acc.x * inv + b2[cg], acc.y * inv + b2[cg + 1]);
    *reinterpret_cast<float2*>(&g_out2[(size_t)n * 64 + cg]) = o;
}

// ---------------- prediction head: 32 batch elems / block (pw1 L1-resident) ----------------
__global__ void k_head(const int* __restrict__ uids, const int* __restrict__ iids,
                       const float* __restrict__ uemb,
                       const float* __restrict__ pw1, const float* __restrict__ pb1,
                       const float* __restrict__ pw2, const float* __restrict__ pb2,
                       float* __restrict__ out) {
    __shared__ float cs[8][192];
    int t = threadIdx.x, w = t >> 5, lane = t & 31;
    float bias0 = pb1[lane], bias1 = pb1[lane + 32];
    float w2a = pw2[lane], w2b = pw2[lane + 32];
    float bout = pb2[0];
    for (int bi = 0; bi < 4; bi++) {
        int b = blockIdx.x * 32 + w * 4 + bi;
        int uid = uids[b];
        int iid = iids[b];
        for (int idx = lane; idx < 192; idx += 32) {
            float v;
            if (idx < 64) v = uemb[(size_t)uid * 64 + idx];
            else if (idx < 128) v = g_out2[(size_t)(NUU + iid) * 64 + (idx - 64)];
            else v = g_out2[(size_t)uid * 64 + (idx - 128)];
            cs[w][idx] = v;
        }
        __syncwarp();
        float a0 = bias0, a1 = bias1;
        for (int k = 0; k < 192; k++) {
            float c = cs[w][k];
            a0 += c * __ldg(&pw1[(size_t)k * 64 + lane]);
            a1 += c * __ldg(&pw1[(size_t)k * 64 + lane + 32]);
        }
        a0 = fmaxf(a0, 0.f);
        a1 = fmaxf(a1, 0.f);
        float p = a0 * w2a + a1 * w2b;
        p = warpSumAll(p);
        if (lane == 0) out[b] = p + bout;
        __syncwarp();
    }
}

// ---------------- launch ----------------
extern "C" void kernel_launch(void* const* d_in, const int* in_sizes, int n_in,
                              void* d_out, int out_size) {
    const int*   user_ids = (const int*)d_in[0];
    const int*   item_ids = (const int*)d_in[1];
    const float* content  = (const float*)d_in[2];
    const int*   edge_idx = (const int*)d_in[3];
    const float* uemb     = (const float*)d_in[4];
    const float* iemb     = (const float*)d_in[5];
    const float* cp_w     = (const float*)d_in[6];
    const float* cp_b     = (const float*)d_in[7];
    const float* w1       = (const float*)d_in[8];
    const float* asrc1    = (const float*)d_in[9];
    const float* adst1    = (const float*)d_in[10];
    const float* b1       = (const float*)d_in[11];
    const float* w2       = (const float*)d_in[12];
    const float* asrc2    = (const float*)d_in[13];
    const float* adst2    = (const float*)d_in[14];
    const float* b2       = (const float*)d_in[15];
    const float* pw1      = (const float*)d_in[16];
    const float* pb1      = (const float*)d_in[17];
    const float* pw2      = (const float*)d_in[18];
    const float* pb2      = (const float*)d_in[19];
    float* out = (float*)d_out;

    k_init<<<1184, 256>>>();
    // content projection: [B,256] @ [256,64] + b
    k_gemm64<CFD, BB, CFD, 0><<<(BB + 127) / 128, 256>>>(content, cp_w, cp_b);
    k_scatter<<<BB, 64>>>(user_ids, item_ids, uemb, iemb);
    // CSR build
    k_hist<<<4096, 256>>>(edge_idx);
    k_scanA<<<NBLK, 1024>>>();
    k_scanB<<<1, 256>>>();
    k_scanC<<<NBLK, 1024>>>();
    k_fill<<<4096, 256>>>(edge_idx);
    // GAT layer 1
    k_gemm1<<<(2 * BB) / 64, 256>>>(w1, user_ids, item_ids);
    k_al1<<<(2 * BB * 32) / 256, 256>>>(asrc1, adst1, user_ids, item_ids);
    k_agg1<<<(NNODE * 32) / 256, 256>>>(b1);
    // GAT layer 2
    k_gemm64<128, NNODE, 128, 1><<<(NNODE + 127) / 128, 256>>>(nullptr, w2, nullptr);
    k_al2<<<(NNODE * 32) / 256, 256>>>(asrc2, adst2);
    k_agg2<<<(2 * BB * 32) / 256, 256>>>(b2, user_ids, item_ids);
    // prediction head
    k_head<<<BB / 32, 256>>>(user_ids, item_ids, uemb, pw1, pb1, pw2, pb2, out);
}

// round 14
// speedup vs baseline: 1.1807x; 1.1807x over previous
#include <cuda_runtime.h>
#include <math.h>

#define DD   64
#define NUU  100000
#define NII  50000
#define NNODE 150000
#define BB   16384
#define CFD  256
#define EE   2000000
#define ETOT (EE + NNODE)           // 2,150,000 (edges + self loops)
#define NBLK 147                    // ceil(NNODE/1024)
#define ACTBIT 0x40000000
#define SRCMASK 0x3FFFFFFF

// ---------------- scratch (device globals; no runtime allocation) ----------------
__device__ __align__(16) float g_x[(size_t)NNODE * 128];    // layer-1 input; reused as h1
__device__ __align__(16) float g_xw1[(size_t)NNODE * 128];  // x @ W1 (only active rows valid)
__device__ __align__(16) float g_xw2[(size_t)NNODE * 64];   // h1 @ W2
__device__ __align__(16) float g_out2[(size_t)NNODE * 64];  // layer-2 output (active dst rows)
__device__ __align__(16) float g_cemb[(size_t)BB * 64];     // content projection
__device__ __align__(16) float g_als1[NNODE * 2];
__device__ __align__(16) float g_ald1[NNODE * 2];
__device__ __align__(16) float g_als2[NNODE];
__device__ __align__(16) float g_ald2[NNODE];
__device__ __align__(16) unsigned char g_active[NNODE];
__device__ __align__(16) int   g_cnt[NNODE];
__device__ __align__(16) int   g_rowptr[NNODE + 1];
__device__ __align__(16) int   g_woff[NNODE];
__device__ __align__(16) int   g_srcs[ETOT];
__device__ __align__(16) int   g_bsum[256];
__device__ __align__(16) int   g_bsumx[256];

// ---------------- helpers ----------------
__device__ __forceinline__ float warpSumAll(float v) {
#pragma unroll
    for (int o = 16; o > 0; o >>= 1) v += __shfl_xor_sync(0xffffffffu, v, o);
    return v;
}
__device__ __forceinline__ float half16Sum(float v) {
#pragma unroll
    for (int o = 1; o < 16; o <<= 1) v += __shfl_xor_sync(0xffffffffu, v, o);
    return v;
}
__device__ __forceinline__ float lrelu02(float x) { return x > 0.f ? x : 0.2f * x; }

// ---------------- init: zero logit arrays + active flags, cnt=1 (self loop) ----------------
__global__ void k_init() {
    size_t tid = (size_t)blockIdx.x * blockDim.x + threadIdx.x;
    size_t stride = (size_t)gridDim.x * blockDim.x;
    float4 z = make_float4(0.f, 0.f, 0.f, 0.f);
    float4* pa = reinterpret_cast<float4*>(g_als1);
    float4* pb = reinterpret_cast<float4*>(g_ald1);
    for (size_t i = tid; i < (size_t)NNODE * 2 / 4; i += stride) { pa[i] = z; pb[i] = z; }
    for (size_t i = tid; i < NNODE; i += stride) { g_cnt[i] = 1; g_active[i] = 0; }
}

// ---------------- generic M x 64 GEMM (out = A @ W [+ bias]) ----------------
// MODE 0: cemb = content @ cp_w + cp_b
// MODE 1: xw2  = g_x(h1) @ w2 ; fused epilogue writes als2/ald2 per row
template <int KDIM, int M, int LDA, int MODE>
__global__ void k_gemm64(const float* __restrict__ Aparam,
                         const float* __restrict__ W,
                         const float* __restrict__ bias,
                         const float* __restrict__ asrc,
                         const float* __restrict__ adst) {
    __shared__ float As[16][128];
    __shared__ float Bs[16][64];
    const float* A = (MODE == 1) ? g_x : Aparam;
    float* out = (MODE == 1) ? g_xw2 : g_cemb;

    int t = threadIdx.x;                 // 256 threads
    int rbase = blockIdx.x * 128;
    int ct = t & 15;                     // 16 col-threads * 4 cols = 64
    int rt = t >> 4;                     // 16 row-threads * 8 rows = 128
    float acc[8][4];
#pragma unroll
    for (int i = 0; i < 8; i++)
#pragma unroll
        for (int j = 0; j < 4; j++) acc[i][j] = 0.f;

    for (int kb = 0; kb < KDIM; kb += 16) {
#pragma unroll
        for (int rep = 0; rep < 2; rep++) {
            int idx = t + 256 * rep;     // 512 float4
            int row = idx >> 2, kq = idx & 3;
            int r = rbase + row;
            float4 v = make_float4(0.f, 0.f, 0.f, 0.f);
            if (r < M) v = *reinterpret_cast<const float4*>(&A[(size_t)r * LDA + kb + kq * 4]);
            As[kq * 4 + 0][row] = v.x;
            As[kq * 4 + 1][row] = v.y;
            As[kq * 4 + 2][row] = v.z;
            As[kq * 4 + 3][row] = v.w;
        }
        {
            int kk = t >> 4, col = (t & 15) * 4;
            *reinterpret_cast<float4*>(&Bs[kk][col]) =
                *reinterpret_cast<const float4*>(&W[(size_t)(kb + kk) * 64 + col]);
        }
        __syncthreads();
#pragma unroll
        for (int k = 0; k < 16; k++) {
            float a[8];
            *reinterpret_cast<float4*>(&a[0]) = *reinterpret_cast<float4*>(&As[k][rt * 8]);
            *reinterpret_cast<float4*>(&a[4]) = *reinterpret_cast<float4*>(&As[k][rt * 8 + 4]);
            float4 b = *reinterpret_cast<float4*>(&Bs[k][ct * 4]);
#pragma unroll
            for (int i = 0; i < 8; i++) {
                acc[i][0] += a[i] * b.x;
                acc[i][1] += a[i] * b.y;
                acc[i][2] += a[i] * b.z;
                acc[i][3] += a[i] * b.w;
            }
        }
        __syncthreads();
    }
#pragma unroll
    for (int i = 0; i < 8; i++) {
        int r = rbase + rt * 8 + i;
        if (r < M) {
            float4 v = make_float4(acc[i][0], acc[i][1], acc[i][2], acc[i][3]);
            if (MODE == 0) {
                v.x += bias[ct * 4 + 0];
                v.y += bias[ct * 4 + 1];
                v.z += bias[ct * 4 + 2];
                v.w += bias[ct * 4 + 3];
            }
            *reinterpret_cast<float4*>(&out[(size_t)r * 64 + ct * 4]) = v;
        }
    }
    if (MODE == 1) {
        // fused al2: per-row dot with asrc2/adst2 ([64] flat), 16-lane reduce
        int lane = t & 31;
        float4 asv = *reinterpret_cast<const float4*>(&asrc[ct * 4]);
        float4 adv = *reinterpret_cast<const float4*>(&adst[ct * 4]);
#pragma unroll
        for (int i = 0; i < 8; i++) {
            float ps = acc[i][0] * asv.x + acc[i][1] * asv.y + acc[i][2] * asv.z + acc[i][3] * asv.w;
            float pd = acc[i][0] * adv.x + acc[i][1] * adv.y + acc[i][2] * adv.z + acc[i][3] * adv.w;
            ps = half16Sum(ps);
            pd = half16Sum(pd);
            int r = rbase + rt * 8 + i;
            if ((lane & 15) == 0 && r < M) { g_als2[r] = ps; g_ald2[r] = pd; }
        }
    }
}

// ---------------- scatter embeddings into node features (+ active flags) ----------------
__global__ void k_scatter(const int* __restrict__ uids, const int* __restrict__ iids,
                          const float* __restrict__ uemb, const float* __restrict__ iemb) {
    int b = blockIdx.x;
    int j = threadIdx.x;  // 64
    int uid = uids[b];
    int iid = iids[b];
    g_x[(size_t)uid * 128 + j] = uemb[(size_t)uid * 64 + j];
    g_x[(size_t)uid * 128 + 64 + j] = 0.f;
    g_x[(size_t)(NUU + iid) * 128 + j] = iemb[(size_t)iid * 64 + j];
    g_x[(size_t)(NUU + iid) * 128 + 64 + j] = g_cemb[(size_t)b * 64 + j];
    if (j == 0) { g_active[uid] = 1; g_active[NUU + iid] = 1; }
}

// ---------------- CSR build ----------------
__global__ void k_hist(const int* __restrict__ ei) {
    int stride = gridDim.x * blockDim.x;
    for (int e = blockIdx.x * blockDim.x + threadIdx.x; e < EE; e += stride)
        atomicAdd(&g_cnt[ei[EE + e]], 1);
}

__global__ void k_scanA() {
    __shared__ int sm[1024];
    int t = threadIdx.x;
    int i = blockIdx.x * 1024 + t;
    int v = (i < NNODE) ? g_cnt[i] : 0;
    sm[t] = v;
    __syncthreads();
    for (int o = 1; o < 1024; o <<= 1) {
        int x = (t >= o) ? sm[t - o] : 0;
        __syncthreads();
        sm[t] += x;
        __syncthreads();
    }
    if (i < NNODE) g_rowptr[i] = sm[t] - v;
    if (t == 1023) g_bsum[blockIdx.x] = sm[1023];
}

__global__ void k_scanB() {
    __shared__ int sm[256];
    int t = threadIdx.x;
    int v = (t < NBLK) ? g_bsum[t] : 0;
    sm[t] = v;
    __syncthreads();
    for (int o = 1; o < 256; o <<= 1) {
        int x = (t >= o) ? sm[t - o] : 0;
        __syncthreads();
        sm[t] += x;
        __syncthreads();
    }
    g_bsumx[t] = sm[t] - v;
}

__global__ void k_scanC() {
    int t = threadIdx.x;
    int i = blockIdx.x * 1024 + t;
    if (i < NNODE) {
        int r = g_rowptr[i] + g_bsumx[blockIdx.x];
        g_rowptr[i] = r;
        g_woff[i] = r;
    }
    if (i == 0) g_rowptr[NNODE] = ETOT;
}

// fill CSR; tag each entry with src-activity in bit 30 (single atomic per edge)
__global__ void k_fill(const int* __restrict__ ei) {
    int stride = gridDim.x * blockDim.x;
    for (int i = blockIdx.x * blockDim.x + threadIdx.x; i < ETOT; i += stride) {
        int s, d;
        if (i < EE) { s = ei[i]; d = ei[EE + i]; }
        else { s = d = i - EE; }
        int pos = atomicAdd(&g_woff[d], 1);
        g_srcs[pos] = s | (g_active[s] ? ACTBIT : 0);
    }
}

// ---------------- layer-1 GEMM over the 2B active rows (gather/scatter) ----------------
__global__ void k_gemm1(const float* __restrict__ W,  // w1 [128,128]
                        const int* __restrict__ uids, const int* __restrict__ iids) {
    __shared__ float As[16][64];
    __shared__ float Bs[16][128];
    __shared__ int nodes[64];
    int t = threadIdx.x;                 // 256
    int rbase = blockIdx.x * 64;
    if (t < 64) {
        int r = rbase + t;
        nodes[t] = (r < BB) ? uids[r] : (NUU + iids[r - BB]);
    }
    __syncthreads();
    int ct = t & 31;                     // 32 col-threads * 4 cols = 128
    int rt = t >> 5;                     // 8 row-threads * 8 rows = 64
    float acc[8][4];
#pragma unroll
    for (int i = 0; i < 8; i++)
#pragma unroll
        for (int j = 0; j < 4; j++) acc[i][j] = 0.f;

    for (int kb = 0; kb < 128; kb += 16) {
        {
            int row = t >> 2, kq = t & 3;
            float4 v = *reinterpret_cast<const float4*>(
                &g_x[(size_t)nodes[row] * 128 + kb + kq * 4]);
            As[kq * 4 + 0][row] = v.x;
            As[kq * 4 + 1][row] = v.y;
            As[kq * 4 + 2][row] = v.z;
            As[kq * 4 + 3][row] = v.w;
        }
        {
            int off = t * 8;
            int kk = off >> 7, col = off & 127;
            const float4* p = reinterpret_cast<const float4*>(&W[(size_t)(kb + kk) * 128 + col]);
            *reinterpret_cast<float4*>(&Bs[kk][col]) = p[0];
            *reinterpret_cast<float4*>(&Bs[kk][col + 4]) = p[1];
        }
        __syncthreads();
#pragma unroll
        for (int k = 0; k < 16; k++) {
            float a[8];
            *reinterpret_cast<float4*>(&a[0]) = *reinterpret_cast<float4*>(&As[k][rt * 8]);
            *reinterpret_cast<float4*>(&a[4]) = *reinterpret_cast<float4*>(&As[k][rt * 8 + 4]);
            float4 b = *reinterpret_cast<float4*>(&Bs[k][ct * 4]);
#pragma unroll
            for (int i = 0; i < 8; i++) {
                acc[i][0] += a[i] * b.x;
                acc[i][1] += a[i] * b.y;
                acc[i][2] += a[i] * b.z;
                acc[i][3] += a[i] * b.w;
            }
        }
        __syncthreads();
    }
#pragma unroll
    for (int i = 0; i < 8; i++) {
        int row = rt * 8 + i;
        float4 v = make_float4(acc[i][0], acc[i][1], acc[i][2], acc[i][3]);
        *reinterpret_cast<float4*>(&g_xw1[(size_t)nodes[row] * 128 + ct * 4]) = v;
    }
}

// ---------------- attention logits: layer 1, ACTIVE nodes only ----------------
__global__ void k_al1(const float* __restrict__ asrc, const float* __restrict__ adst,
                      const int* __restrict__ uids, const int* __restrict__ iids) {
    int gt = blockIdx.x * blockDim.x + threadIdx.x;
    int r = gt >> 5, lane = gt & 31;
    if (r >= 2 * BB) return;
    int n = (r < BB) ? uids[r] : (NUU + iids[r - BB]);
    int cg = lane * 4;
    float4 v = *reinterpret_cast<const float4*>(&g_xw1[(size_t)n * 128 + cg]);
    float4 as = *reinterpret_cast<const float4*>(&asrc[cg]);
    float4 ad = *reinterpret_cast<const float4*>(&adst[cg]);
    float ps = v.x * as.x + v.y * as.y + v.z * as.z + v.w * as.w;
    float pd = v.x * ad.x + v.y * ad.y + v.z * ad.z + v.w * ad.w;
#pragma unroll
    for (int o = 8; o > 0; o >>= 1) {
        ps += __shfl_xor_sync(0xffffffffu, ps, o);
        pd += __shfl_xor_sync(0xffffffffu, pd, o);
    }
    if ((lane & 15) == 0) {
        int h = lane >> 4;
        g_als1[(size_t)n * 2 + h] = ps;
        g_ald1[(size_t)n * 2 + h] = pd;
    }
}

// ---------------- layer-1 aggregation (round-6 form: unconditional cached als1 loads,
// ballot-gather over active sources only) ----------------
__global__ void k_agg1(const float* __restrict__ b1) {
    int gt = blockIdx.x * blockDim.x + threadIdx.x;
    int n = gt >> 5, lane = gt & 31;
    if (n >= NNODE) return;
    int beg = g_rowptr[n], end = g_rowptr[n + 1];
    float ad0 = g_ald1[(size_t)n * 2 + 0];
    float ad1 = g_ald1[(size_t)n * 2 + 1];

    int cg = lane * 4;
    bool headHi = (lane >= 16);
    float den0 = 0.f, den1 = 0.f;
    float4 acc = make_float4(0.f, 0.f, 0.f, 0.f);

    for (int c = beg; c < end; c += 32) {
        int i = c + lane;
        bool valid = i < end;
        int sv = valid ? g_srcs[i] : 0;
        int s = sv & SRCMASK;
        float e0 = 0.f, e1 = 0.f;
        if (valid) {
            float2 as = *reinterpret_cast<const float2*>(&g_als1[(size_t)s * 2]);
            e0 = __expf(lrelu02(as.x + ad0));
            e1 = __expf(lrelu02(as.y + ad1));
        }
        den0 += e0;
        den1 += e1;
        unsigned amask = __ballot_sync(0xffffffffu, valid && (sv & ACTBIT));
        while (amask) {
            int j = __ffs(amask) - 1;
            amask &= amask - 1;
            int sj = __shfl_sync(0xffffffffu, s, j);
            float wa = __shfl_sync(0xffffffffu, e0, j);
            float wb = __shfl_sync(0xffffffffu, e1, j);
            float wj = headHi ? wb : wa;
            float4 xv = *reinterpret_cast<const float4*>(&g_xw1[(size_t)sj * 128 + cg]);
            acc.x += wj * xv.x;
            acc.y += wj * xv.y;
            acc.z += wj * xv.z;
            acc.w += wj * xv.w;
        }
    }
    den0 = warpSumAll(den0);
    den1 = warpSumAll(den1);
    float inv = 1.f / ((headHi ? den1 : den0) + 1e-16f);

    float4 bv = *reinterpret_cast<const float4*>(&b1[cg]);
    float4 o;
    o.x = acc.x * inv + bv.x; o.x = o.x > 0.f ? o.x : expm1f(o.x);
    o.y = acc.y * inv + bv.y; o.y = o.y > 0.f ? o.y : expm1f(o.y);
    o.z = acc.z * inv + bv.z; o.z = o.z > 0.f ? o.z : expm1f(o.z);
    o.w = acc.w * inv + bv.w; o.w = o.w > 0.f ? o.w : expm1f(o.w);
    *reinterpret_cast<float4*>(&g_x[(size_t)n * 128 + cg]) = o;  // h1 into g_x
}

// ---------------- layer-2 aggregation: ONLY over the 2B destination nodes the head reads ----------------
__global__ void k_agg2(const float* __restrict__ b2,
                       const int* __restrict__ uids, const int* __restrict__ iids) {
    int gt = blockIdx.x * blockDim.x + threadIdx.x;
    int r = gt >> 5, lane = gt & 31;
    if (r >= 2 * BB) return;
    int n = (r < BB) ? uids[r] : (NUU + iids[r - BB]);
    int beg = g_rowptr[n], end = g_rowptr[n + 1];
    float ad = g_ald2[n];

    int cg = lane * 2;
    float den = 0.f;
    float2 acc = make_float2(0.f, 0.f);
    for (int c = beg; c < end; c += 32) {
        int i = c + lane;
        bool valid = i < end;
        int s = (valid ? g_srcs[i] : 0) & SRCMASK;
        float e = valid ? __expf(lrelu02(g_als2[s] + ad)) : 0.f;
        den += e;
        int cnt = min(32, end - c);
        for (int j = 0; j < cnt; j++) {
            int sj = __shfl_sync(0xffffffffu, s, j);
            float wj = __shfl_sync(0xffffffffu, e, j);
            float2 xv = *reinterpret_cast<const float2*>(&g_xw2[(size_t)sj * 64 + cg]);
            acc.x += wj * xv.x;
            acc.y += wj * xv.y;
        }
    }
    den = warpSumAll(den);
    float inv = 1.f / (den + 1e-16f);
    float2 o = make_float2(acc.x * inv + b2[cg], acc.y * inv + b2[cg + 1]);
    *reinterpret_cast<float2*>(&g_out2[(size_t)n * 64 + cg]) = o;
}

// ---------------- prediction head (round-6 form: warp per batch element) ----------------
__global__ void k_head(const int* __restrict__ uids, const int* __restrict__ iids,
                       const float* __restrict__ uemb,
                       const float* __restrict__ pw1, const float* __restrict__ pb1,
                       const float* __restrict__ pw2, const float* __restrict__ pb2,
                       float* __restrict__ out) {
    __shared__ float cs[8][192];
    int t = threadIdx.x, w = t >> 5, lane = t & 31;
    int b = blockIdx.x * 8 + w;
    int uid = uids[b];
    int iid = iids[b];
    for (int idx = lane; idx < 192; idx += 32) {
        float v;
        if (idx < 64) v = uemb[(size_t)uid * 64 + idx];
        else if (idx < 128) v = g_out2[(size_t)(NUU + iid) * 64 + (idx - 64)];
        else v = g_out2[(size_t)uid * 64 + (idx - 128)];
        cs[w][idx] = v;
    }
    __syncwarp();
    float a0 = pb1[lane], a1 = pb1[lane + 32];
    for (int k = 0; k < 192; k++) {
        float c = cs[w][k];
        a0 += c * pw1[(size_t)k * 64 + lane];
        a1 += c * pw1[(size_t)k * 64 + lane + 32];
    }
    a0 = fmaxf(a0, 0.f);
    a1 = fmaxf(a1, 0.f);
    float p = a0 * pw2[lane] + a1 * pw2[lane + 32];
    p = warpSumAll(p);
    if (lane == 0) out[b] = p + pb2[0];
}

// ---------------- launch ----------------
extern "C" void kernel_launch(void* const* d_in, const int* in_sizes, int n_in,
                              void* d_out, int out_size) {
    const int*   user_ids = (const int*)d_in[0];
    const int*   item_ids = (const int*)d_in[1];
    const float* content  = (const float*)d_in[2];
    const int*   edge_idx = (const int*)d_in[3];
    const float* uemb     = (const float*)d_in[4];
    const float* iemb     = (const float*)d_in[5];
    const float* cp_w     = (const float*)d_in[6];
    const float* cp_b     = (const float*)d_in[7];
    const float* w1       = (const float*)d_in[8];
    const float* asrc1    = (const float*)d_in[9];
    const float* adst1    = (const float*)d_in[10];
    const float* b1       = (const float*)d_in[11];
    const float* w2       = (const float*)d_in[12];
    const float* asrc2    = (const float*)d_in[13];
    const float* adst2    = (const float*)d_in[14];
    const float* b2       = (const float*)d_in[15];
    const float* pw1      = (const float*)d_in[16];
    const float* pb1      = (const float*)d_in[17];
    const float* pw2      = (const float*)d_in[18];
    const float* pb2      = (const float*)d_in[19];
    float* out = (float*)d_out;

    k_init<<<1184, 256>>>();
    // content projection: [B,256] @ [256,64] + b
    k_gemm64<CFD, BB, CFD, 0><<<(BB + 127) / 128, 256>>>(content, cp_w, cp_b, nullptr, nullptr);
    k_scatter<<<BB, 64>>>(user_ids, item_ids, uemb, iemb);
    // CSR build
    k_hist<<<4096, 256>>>(edge_idx);
    k_scanA<<<NBLK, 1024>>>();
    k_scanB<<<1, 256>>>();
    k_scanC<<<NBLK, 1024>>>();
    k_fill<<<4096, 256>>>(edge_idx);
    // GAT layer 1
    k_gemm1<<<(2 * BB) / 64, 256>>>(w1, user_ids, item_ids);
    k_al1<<<(2 * BB * 32) / 256, 256>>>(asrc1, adst1, user_ids, item_ids);
    k_agg1<<<(NNODE * 32) / 256, 256>>>(b1);
    // GAT layer 2 (al2 fused into GEMM epilogue)
    k_gemm64<128, NNODE, 128, 1><<<(NNODE + 127) / 128, 256>>>(nullptr, w2, nullptr, asrc2, adst2);
    k_agg2<<<(2 * BB * 32) / 256, 256>>>(b2, user_ids, item_ids);
    // prediction head
    k_head<<<BB / 8, 256>>>(user_ids, item_ids, uemb, pw1, pb1, pw2, pb2, out);
}

// round 15
// speedup vs baseline: 1.2697x; 1.0754x over previous
#include <cuda_runtime.h>
#include <math.h>

#define DD   64
#define NUU  100000
#define NII  50000
#define NNODE 150000
#define BB   16384
#define CFD  256
#define EE   2000000
#define ETOT (EE + NNODE)           // 2,150,000 (edges + self loops)
#define NBLK 147                    // ceil(NNODE/1024)
#define ACTBIT 0x40000000
#define SRCMASK 0x3FFFFFFF

// ---------------- scratch (device globals; no runtime allocation) ----------------
__device__ __align__(16) float g_x[(size_t)NNODE * 128];    // layer-1 input; reused as h1
__device__ __align__(16) float g_xw1[(size_t)NNODE * 128];  // x @ W1 (only active rows valid)
__device__ __align__(16) float g_xw2[(size_t)NNODE * 64];   // h1 @ W2
__device__ __align__(16) float g_out2[(size_t)NNODE * 64];  // layer-2 output (active dst rows)
__device__ __align__(16) float g_cemb[(size_t)BB * 64];     // content projection
__device__ __align__(16) float g_als1[NNODE * 2];
__device__ __align__(16) float g_ald1[NNODE * 2];
__device__ __align__(16) float g_als2[NNODE];
__device__ __align__(16) float g_ald2[NNODE];
__device__ __align__(16) unsigned char g_active[NNODE];
__device__ __align__(16) int   g_cnt[NNODE];
__device__ __align__(16) int   g_rowptr[NNODE + 1];
__device__ __align__(16) int   g_woff[NNODE];
__device__ __align__(16) int   g_srcs[ETOT];
__device__ __align__(16) int   g_bsum[256];
__device__ __align__(16) int   g_bsumx[256];

// ---------------- helpers ----------------
__device__ __forceinline__ float warpSumAll(float v) {
#pragma unroll
    for (int o = 16; o > 0; o >>= 1) v += __shfl_xor_sync(0xffffffffu, v, o);
    return v;
}
__device__ __forceinline__ float half16Sum(float v) {
#pragma unroll
    for (int o = 1; o < 16; o <<= 1) v += __shfl_xor_sync(0xffffffffu, v, o);
    return v;
}
__device__ __forceinline__ float lrelu02(float x) { return x > 0.f ? x : 0.2f * x; }

// ---------------- init: zero logit arrays + active flags, cnt=1 (self loop) ----------------
__global__ void k_init() {
    size_t tid = (size_t)blockIdx.x * blockDim.x + threadIdx.x;
    size_t stride = (size_t)gridDim.x * blockDim.x;
    float4 z = make_float4(0.f, 0.f, 0.f, 0.f);
    float4* pa = reinterpret_cast<float4*>(g_als1);
    float4* pb = reinterpret_cast<float4*>(g_ald1);
    for (size_t i = tid; i < (size_t)NNODE * 2 / 4; i += stride) { pa[i] = z; pb[i] = z; }
    for (size_t i = tid; i < NNODE; i += stride) { g_cnt[i] = 1; g_active[i] = 0; }
}

// ---------------- generic M x 64 GEMM (out = A @ W [+ bias]) ----------------
// MODE 0: cemb = content @ cp_w + cp_b
// MODE 1: xw2  = g_x(h1) @ w2 ; fused epilogue writes als2/ald2 per row
template <int KDIM, int M, int LDA, int MODE>
__global__ void k_gemm64(const float* __restrict__ Aparam,
                         const float* __restrict__ W,
                         const float* __restrict__ bias,
                         const float* __restrict__ asrc,
                         const float* __restrict__ adst) {
    __shared__ float As[16][128];
    __shared__ float Bs[16][64];
    const float* A = (MODE == 1) ? g_x : Aparam;
    float* out = (MODE == 1) ? g_xw2 : g_cemb;

    int t = threadIdx.x;                 // 256 threads
    int rbase = blockIdx.x * 128;
    int ct = t & 15;                     // 16 col-threads * 4 cols = 64
    int rt = t >> 4;                     // 16 row-threads * 8 rows = 128
    float acc[8][4];
#pragma unroll
    for (int i = 0; i < 8; i++)
#pragma unroll
        for (int j = 0; j < 4; j++) acc[i][j] = 0.f;

    for (int kb = 0; kb < KDIM; kb += 16) {
#pragma unroll
        for (int rep = 0; rep < 2; rep++) {
            int idx = t + 256 * rep;     // 512 float4
            int row = idx >> 2, kq = idx & 3;
            int r = rbase + row;
            float4 v = make_float4(0.f, 0.f, 0.f, 0.f);
            if (r < M) v = *reinterpret_cast<const float4*>(&A[(size_t)r * LDA + kb + kq * 4]);
            As[kq * 4 + 0][row] = v.x;
            As[kq * 4 + 1][row] = v.y;
            As[kq * 4 + 2][row] = v.z;
            As[kq * 4 + 3][row] = v.w;
        }
        {
            int kk = t >> 4, col = (t & 15) * 4;
            *reinterpret_cast<float4*>(&Bs[kk][col]) =
                *reinterpret_cast<const float4*>(&W[(size_t)(kb + kk) * 64 + col]);
        }
        __syncthreads();
#pragma unroll
        for (int k = 0; k < 16; k++) {
            float a[8];
            *reinterpret_cast<float4*>(&a[0]) = *reinterpret_cast<float4*>(&As[k][rt * 8]);
            *reinterpret_cast<float4*>(&a[4]) = *reinterpret_cast<float4*>(&As[k][rt * 8 + 4]);
            float4 b = *reinterpret_cast<float4*>(&Bs[k][ct * 4]);
#pragma unroll
            for (int i = 0; i < 8; i++) {
                acc[i][0] += a[i] * b.x;
                acc[i][1] += a[i] * b.y;
                acc[i][2] += a[i] * b.z;
                acc[i][3] += a[i] * b.w;
            }
        }
        __syncthreads();
    }
#pragma unroll
    for (int i = 0; i < 8; i++) {
        int r = rbase + rt * 8 + i;
        if (r < M) {
            float4 v = make_float4(acc[i][0], acc[i][1], acc[i][2], acc[i][3]);
            if (MODE == 0) {
                v.x += bias[ct * 4 + 0];
                v.y += bias[ct * 4 + 1];
                v.z += bias[ct * 4 + 2];
                v.w += bias[ct * 4 + 3];
            }
            *reinterpret_cast<float4*>(&out[(size_t)r * 64 + ct * 4]) = v;
        }
    }
    if (MODE == 1) {
        // fused al2: per-row dot with asrc2/adst2 ([64] flat), 16-lane reduce
        int lane = t & 31;
        float4 asv = *reinterpret_cast<const float4*>(&asrc[ct * 4]);
        float4 adv = *reinterpret_cast<const float4*>(&adst[ct * 4]);
#pragma unroll
        for (int i = 0; i < 8; i++) {
            float ps = acc[i][0] * asv.x + acc[i][1] * asv.y + acc[i][2] * asv.z + acc[i][3] * asv.w;
            float pd = acc[i][0] * adv.x + acc[i][1] * adv.y + acc[i][2] * adv.z + acc[i][3] * adv.w;
            ps = half16Sum(ps);
            pd = half16Sum(pd);
            int r = rbase + rt * 8 + i;
            if ((lane & 15) == 0 && r < M) { g_als2[r] = ps; g_ald2[r] = pd; }
        }
    }
}

// ---------------- scatter embeddings into node features (+ active flags) ----------------
__global__ void k_scatter(const int* __restrict__ uids, const int* __restrict__ iids,
                          const float* __restrict__ uemb, const float* __restrict__ iemb) {
    int b = blockIdx.x;
    int j = threadIdx.x;  // 64
    int uid = uids[b];
    int iid = iids[b];
    g_x[(size_t)uid * 128 + j] = uemb[(size_t)uid * 64 + j];
    g_x[(size_t)uid * 128 + 64 + j] = 0.f;
    g_x[(size_t)(NUU + iid) * 128 + j] = iemb[(size_t)iid * 64 + j];
    g_x[(size_t)(NUU + iid) * 128 + 64 + j] = g_cemb[(size_t)b * 64 + j];
    if (j == 0) { g_active[uid] = 1; g_active[NUU + iid] = 1; }
}

// ---------------- CSR build ----------------
__global__ void k_hist(const int* __restrict__ ei) {
    int stride = gridDim.x * blockDim.x;
    for (int e = blockIdx.x * blockDim.x + threadIdx.x; e < EE; e += stride)
        atomicAdd(&g_cnt[ei[EE + e]], 1);
}

__global__ void k_scanA() {
    __shared__ int sm[1024];
    int t = threadIdx.x;
    int i = blockIdx.x * 1024 + t;
    int v = (i < NNODE) ? g_cnt[i] : 0;
    sm[t] = v;
    __syncthreads();
    for (int o = 1; o < 1024; o <<= 1) {
        int x = (t >= o) ? sm[t - o] : 0;
        __syncthreads();
        sm[t] += x;
        __syncthreads();
    }
    if (i < NNODE) g_rowptr[i] = sm[t] - v;
    if (t == 1023) g_bsum[blockIdx.x] = sm[1023];
}

__global__ void k_scanB() {
    __shared__ int sm[256];
    int t = threadIdx.x;
    int v = (t < NBLK) ? g_bsum[t] : 0;
    sm[t] = v;
    __syncthreads();
    for (int o = 1; o < 256; o <<= 1) {
        int x = (t >= o) ? sm[t - o] : 0;
        __syncthreads();
        sm[t] += x;
        __syncthreads();
    }
    g_bsumx[t] = sm[t] - v;
}

__global__ void k_scanC() {
    int t = threadIdx.x;
    int i = blockIdx.x * 1024 + t;
    if (i < NNODE) {
        int r = g_rowptr[i] + g_bsumx[blockIdx.x];
        g_rowptr[i] = r;
        g_woff[i] = r;
    }
    if (i == 0) g_rowptr[NNODE] = ETOT;
}

// fill CSR; tag each entry with src-activity in bit 30 (single atomic per edge)
__global__ void k_fill(const int* __restrict__ ei) {
    int stride = gridDim.x * blockDim.x;
    for (int i = blockIdx.x * blockDim.x + threadIdx.x; i < ETOT; i += stride) {
        int s, d;
        if (i < EE) { s = ei[i]; d = ei[EE + i]; }
        else { s = d = i - EE; }
        int pos = atomicAdd(&g_woff[d], 1);
        g_srcs[pos] = s | (g_active[s] ? ACTBIT : 0);
    }
}

// ---------------- layer-1 GEMM over the 2B active rows (gather/scatter) ----------------
__global__ void k_gemm1(const float* __restrict__ W,  // w1 [128,128]
                        const int* __restrict__ uids, const int* __restrict__ iids) {
    __shared__ float As[16][64];
    __shared__ float Bs[16][128];
    __shared__ int nodes[64];
    int t = threadIdx.x;                 // 256
    int rbase = blockIdx.x * 64;
    if (t < 64) {
        int r = rbase + t;
        nodes[t] = (r < BB) ? uids[r] : (NUU + iids[r - BB]);
    }
    __syncthreads();
    int ct = t & 31;                     // 32 col-threads * 4 cols = 128
    int rt = t >> 5;                     // 8 row-threads * 8 rows = 64
    float acc[8][4];
#pragma unroll
    for (int i = 0; i < 8; i++)
#pragma unroll
        for (int j = 0; j < 4; j++) acc[i][j] = 0.f;

    for (int kb = 0; kb < 128; kb += 16) {
        {
            int row = t >> 2, kq = t & 3;
            float4 v = *reinterpret_cast<const float4*>(
                &g_x[(size_t)nodes[row] * 128 + kb + kq * 4]);
            As[kq * 4 + 0][row] = v.x;
            As[kq * 4 + 1][row] = v.y;
            As[kq * 4 + 2][row] = v.z;
            As[kq * 4 + 3][row] = v.w;
        }
        {
            int off = t * 8;
            int kk = off >> 7, col = off & 127;
            const float4* p = reinterpret_cast<const float4*>(&W[(size_t)(kb + kk) * 128 + col]);
            *reinterpret_cast<float4*>(&Bs[kk][col]) = p[0];
            *reinterpret_cast<float4*>(&Bs[kk][col + 4]) = p[1];
        }
        __syncthreads();
#pragma unroll
        for (int k = 0; k < 16; k++) {
            float a[8];
            *reinterpret_cast<float4*>(&a[0]) = *reinterpret_cast<float4*>(&As[k][rt * 8]);
            *reinterpret_cast<float4*>(&a[4]) = *reinterpret_cast<float4*>(&As[k][rt * 8 + 4]);
            float4 b = *reinterpret_cast<float4*>(&Bs[k][ct * 4]);
#pragma unroll
            for (int i = 0; i < 8; i++) {
                acc[i][0] += a[i] * b.x;
                acc[i][1] += a[i] * b.y;
                acc[i][2] += a[i] * b.z;
                acc[i][3] += a[i] * b.w;
            }
        }
        __syncthreads();
    }
#pragma unroll
    for (int i = 0; i < 8; i++) {
        int row = rt * 8 + i;
        float4 v = make_float4(acc[i][0], acc[i][1], acc[i][2], acc[i][3]);
        *reinterpret_cast<float4*>(&g_xw1[(size_t)nodes[row] * 128 + ct * 4]) = v;
    }
}

// ---------------- attention logits: layer 1, ACTIVE nodes only ----------------
__global__ void k_al1(const float* __restrict__ asrc, const float* __restrict__ adst,
                      const int* __restrict__ uids, const int* __restrict__ iids) {
    int gt = blockIdx.x * blockDim.x + threadIdx.x;
    int r = gt >> 5, lane = gt & 31;
    if (r >= 2 * BB) return;
    int n = (r < BB) ? uids[r] : (NUU + iids[r - BB]);
    int cg = lane * 4;
    float4 v = *reinterpret_cast<const float4*>(&g_xw1[(size_t)n * 128 + cg]);
    float4 as = *reinterpret_cast<const float4*>(&asrc[cg]);
    float4 ad = *reinterpret_cast<const float4*>(&adst[cg]);
    float ps = v.x * as.x + v.y * as.y + v.z * as.z + v.w * as.w;
    float pd = v.x * ad.x + v.y * ad.y + v.z * ad.z + v.w * ad.w;
#pragma unroll
    for (int o = 8; o > 0; o >>= 1) {
        ps += __shfl_xor_sync(0xffffffffu, ps, o);
        pd += __shfl_xor_sync(0xffffffffu, pd, o);
    }
    if ((lane & 15) == 0) {
        int h = lane >> 4;
        g_als1[(size_t)n * 2 + h] = ps;
        g_ald1[(size_t)n * 2 + h] = pd;
    }
}

// ---------------- layer-1 aggregation (unconditional cached als1 loads,
// ballot-gather over active sources only) ----------------
__global__ void k_agg1(const float* __restrict__ b1) {
    int gt = blockIdx.x * blockDim.x + threadIdx.x;
    int n = gt >> 5, lane = gt & 31;
    if (n >= NNODE) return;
    int beg = g_rowptr[n], end = g_rowptr[n + 1];
    float ad0 = g_ald1[(size_t)n * 2 + 0];
    float ad1 = g_ald1[(size_t)n * 2 + 1];

    int cg = lane * 4;
    bool headHi = (lane >= 16);
    float den0 = 0.f, den1 = 0.f;
    float4 acc = make_float4(0.f, 0.f, 0.f, 0.f);

    for (int c = beg; c < end; c += 32) {
        int i = c + lane;
        bool valid = i < end;
        int sv = valid ? g_srcs[i] : 0;
        int s = sv & SRCMASK;
        float e0 = 0.f, e1 = 0.f;
        if (valid) {
            float2 as = *reinterpret_cast<const float2*>(&g_als1[(size_t)s * 2]);
            e0 = __expf(lrelu02(as.x + ad0));
            e1 = __expf(lrelu02(as.y + ad1));
        }
        den0 += e0;
        den1 += e1;
        unsigned amask = __ballot_sync(0xffffffffu, valid && (sv & ACTBIT));
        while (amask) {
            int j = __ffs(amask) - 1;
            amask &= amask - 1;
            int sj = __shfl_sync(0xffffffffu, s, j);
            float wa = __shfl_sync(0xffffffffu, e0, j);
            float wb = __shfl_sync(0xffffffffu, e1, j);
            float wj = headHi ? wb : wa;
            float4 xv = *reinterpret_cast<const float4*>(&g_xw1[(size_t)sj * 128 + cg]);
            acc.x += wj * xv.x;
            acc.y += wj * xv.y;
            acc.z += wj * xv.z;
            acc.w += wj * xv.w;
        }
    }
    den0 = warpSumAll(den0);
    den1 = warpSumAll(den1);
    float inv = 1.f / ((headHi ? den1 : den0) + 1e-16f);

    float4 bv = *reinterpret_cast<const float4*>(&b1[cg]);
    float4 o;
    o.x = acc.x * inv + bv.x; o.x = o.x > 0.f ? o.x : expm1f(o.x);
    o.y = acc.y * inv + bv.y; o.y = o.y > 0.f ? o.y : expm1f(o.y);
    o.z = acc.z * inv + bv.z; o.z = o.z > 0.f ? o.z : expm1f(o.z);
    o.w = acc.w * inv + bv.w; o.w = o.w > 0.f ? o.w : expm1f(o.w);
    *reinterpret_cast<float4*>(&g_x[(size_t)n * 128 + cg]) = o;  // h1 into g_x
}

// ---------------- layer-2 aggregation: ONLY over the 2B destination nodes the head reads ----------------
__global__ void k_agg2(const float* __restrict__ b2,
                       const int* __restrict__ uids, const int* __restrict__ iids) {
    int gt = blockIdx.x * blockDim.x + threadIdx.x;
    int r = gt >> 5, lane = gt & 31;
    if (r >= 2 * BB) return;
    int n = (r < BB) ? uids[r] : (NUU + iids[r - BB]);
    int beg = g_rowptr[n], end = g_rowptr[n + 1];
    float ad = g_ald2[n];

    int cg = lane * 2;
    float den = 0.f;
    float2 acc = make_float2(0.f, 0.f);
    for (int c = beg; c < end; c += 32) {
        int i = c + lane;
        bool valid = i < end;
        int s = (valid ? g_srcs[i] : 0) & SRCMASK;
        float e = valid ? __expf(lrelu02(g_als2[s] + ad)) : 0.f;
        den += e;
        int cnt = min(32, end - c);
        for (int j = 0; j < cnt; j++) {
            int sj = __shfl_sync(0xffffffffu, s, j);
            float wj = __shfl_sync(0xffffffffu, e, j);
            float2 xv = *reinterpret_cast<const float2*>(&g_xw2[(size_t)sj * 64 + cg]);
            acc.x += wj * xv.x;
            acc.y += wj * xv.y;
        }
    }
    den = warpSumAll(den);
    float inv = 1.f / (den + 1e-16f);
    float2 o = make_float2(acc.x * inv + b2[cg], acc.y * inv + b2[cg + 1]);
    *reinterpret_cast<float2*>(&g_out2[(size_t)n * 64 + cg]) = o;
}

// ---------------- prediction head (warp per batch element) ----------------
__global__ void k_head(const int* __restrict__ uids, const int* __restrict__ iids,
                       const float* __restrict__ uemb,
                       const float* __restrict__ pw1, const float* __restrict__ pb1,
                       const float* __restrict__ pw2, const float* __restrict__ pb2,
                       float* __restrict__ out) {
    __shared__ float cs[8][192];
    int t = threadIdx.x, w = t >> 5, lane = t & 31;
    int b = blockIdx.x * 8 + w;
    int uid = uids[b];
    int iid = iids[b];
    for (int idx = lane; idx < 192; idx += 32) {
        float v;
        if (idx < 64) v = uemb[(size_t)uid * 64 + idx];
        else if (idx < 128) v = g_out2[(size_t)(NUU + iid) * 64 + (idx - 64)];
        else v = g_out2[(size_t)uid * 64 + (idx - 128)];
        cs[w][idx] = v;
    }
    __syncwarp();
    float a0 = pb1[lane], a1 = pb1[lane + 32];
    for (int k = 0; k < 192; k++) {
        float c = cs[w][k];
        a0 += c * pw1[(size_t)k * 64 + lane];
        a1 += c * pw1[(size_t)k * 64 + lane + 32];
    }
    a0 = fmaxf(a0, 0.f);
    a1 = fmaxf(a1, 0.f);
    float p = a0 * pw2[lane] + a1 * pw2[lane + 32];
    p = warpSumAll(p);
    if (lane == 0) out[b] = p + pb2[0];
}

// ---------------- launch: two overlapped chains via capture-legal fork/join ----------------
extern "C" void kernel_launch(void* const* d_in, const int* in_sizes, int n_in,
                              void* d_out, int out_size) {
    const int*   user_ids = (const int*)d_in[0];
    const int*   item_ids = (const int*)d_in[1];
    const float* content  = (const float*)d_in[2];
    const int*   edge_idx = (const int*)d_in[3];
    const float* uemb     = (const float*)d_in[4];
    const float* iemb     = (const float*)d_in[5];
    const float* cp_w     = (const float*)d_in[6];
    const float* cp_b     = (const float*)d_in[7];
    const float* w1       = (const float*)d_in[8];
    const float* asrc1    = (const float*)d_in[9];
    const float* adst1    = (const float*)d_in[10];
    const float* b1       = (const float*)d_in[11];
    const float* w2       = (const float*)d_in[12];
    const float* asrc2    = (const float*)d_in[13];
    const float* adst2    = (const float*)d_in[14];
    const float* b2       = (const float*)d_in[15];
    const float* pw1      = (const float*)d_in[16];
    const float* pb1      = (const float*)d_in[17];
    const float* pw2      = (const float*)d_in[18];
    const float* pb2      = (const float*)d_in[19];
    float* out = (float*)d_out;

    // Forked stream + events (host-side objects; created per call — kernel_launch
    // is invoked only for correctness + capture, never during timed replays).
    cudaStream_t s2;
    cudaStreamCreateWithFlags(&s2, cudaStreamNonBlocking);
    cudaEvent_t evInit, evScatter, evFeat;
    cudaEventCreateWithFlags(&evInit, cudaEventDisableTiming);
    cudaEventCreateWithFlags(&evScatter, cudaEventDisableTiming);
    cudaEventCreateWithFlags(&evFeat, cudaEventDisableTiming);

    // init on the capturing (legacy) stream, then fork
    k_init<<<1184, 256>>>();
    cudaEventRecord(evInit, 0);
    cudaStreamWaitEvent(s2, evInit, 0);

    // --- feature chain on s2 ---
    k_gemm64<CFD, BB, CFD, 0><<<(BB + 127) / 128, 256, 0, s2>>>(content, cp_w, cp_b, nullptr, nullptr);
    k_scatter<<<BB, 64, 0, s2>>>(user_ids, item_ids, uemb, iemb);
    cudaEventRecord(evScatter, s2);                       // g_active ready
    k_gemm1<<<(2 * BB) / 64, 256, 0, s2>>>(w1, user_ids, item_ids);
    k_al1<<<(2 * BB * 32) / 256, 256, 0, s2>>>(asrc1, adst1, user_ids, item_ids);
    cudaEventRecord(evFeat, s2);                          // join point

    // --- CSR chain on legacy stream (overlaps with feature chain) ---
    k_hist<<<4096, 256>>>(edge_idx);
    k_scanA<<<NBLK, 1024>>>();
    k_scanB<<<1, 256>>>();
    k_scanC<<<NBLK, 1024>>>();
    cudaStreamWaitEvent(0, evScatter, 0);                 // fill needs g_active
    k_fill<<<4096, 256>>>(edge_idx);

    // --- join: aggregation onward on legacy stream ---
    cudaStreamWaitEvent(0, evFeat, 0);
    k_agg1<<<(NNODE * 32) / 256, 256>>>(b1);
    k_gemm64<128, NNODE, 128, 1><<<(NNODE + 127) / 128, 256>>>(nullptr, w2, nullptr, asrc2, adst2);
    k_agg2<<<(2 * BB * 32) / 256, 256>>>(b2, user_ids, item_ids);
    k_head<<<BB / 8, 256>>>(user_ids, item_ids, uemb, pw1, pb1, pw2, pb2, out);
}

// round 16
// speedup vs baseline: 1.3285x; 1.0463x over previous
#include <cuda_runtime.h>
#include <math.h>

#define DD   64
#define NUU  100000
#define NII  50000
#define NNODE 150000
#define BB   16384
#define CFD  256
#define EE   2000000
#define ETOT (EE + NNODE)           // 2,150,000 (edges + self loops)
#define NBLK 147                    // ceil(NNODE/1024)
#define ACTBIT 0x40000000
#define SRCMASK 0x3FFFFFFF

// ---------------- scratch (device globals; no runtime allocation) ----------------
__device__ __align__(16) float g_x[(size_t)NNODE * 128];    // layer-1 input; reused as h1
__device__ __align__(16) float g_xw1[(size_t)NNODE * 128];  // x @ W1 (only active rows valid)
__device__ __align__(16) float g_xw2[(size_t)NNODE * 64];   // h1 @ W2
__device__ __align__(16) float g_out2[(size_t)NNODE * 64];  // layer-2 output (active dst rows)
__device__ __align__(16) float g_cemb[(size_t)BB * 64];     // content projection
__device__ __align__(16) float g_als1[NNODE * 2];
__device__ __align__(16) float g_ald1[NNODE * 2];
__device__ __align__(16) float g_als2[NNODE];
__device__ __align__(16) float g_ald2[NNODE];
__device__ __align__(16) unsigned char g_active[NNODE];
__device__ __align__(16) int   g_cnt[NNODE];
__device__ __align__(16) int   g_rowptr[NNODE + 1];
__device__ __align__(16) int   g_woff[NNODE];
__device__ __align__(16) int   g_srcs[ETOT];
__device__ __align__(16) int   g_bsum[256];
__device__ __align__(16) int   g_bsumx[256];

// ---------------- helpers ----------------
__device__ __forceinline__ float warpSumAll(float v) {
#pragma unroll
    for (int o = 16; o > 0; o >>= 1) v += __shfl_xor_sync(0xffffffffu, v, o);
    return v;
}
__device__ __forceinline__ float half16Sum(float v) {
#pragma unroll
    for (int o = 1; o < 16; o <<= 1) v += __shfl_xor_sync(0xffffffffu, v, o);
    return v;
}
__device__ __forceinline__ float lrelu02(float x) { return x > 0.f ? x : 0.2f * x; }

// ---- packed f32x2 (FFMA2 path; PTX-only per sm_103a SASS quickref) ----
__device__ __forceinline__ unsigned long long pack2(float lo, float hi) {
    unsigned long long d;
    asm("mov.b64 %0, {%1, %2};" : "=l"(d) : "f"(lo), "f"(hi));
    return d;
}
__device__ __forceinline__ void fma2(unsigned long long& d,
                                     unsigned long long a, unsigned long long b) {
    asm("fma.rn.f32x2 %0, %1, %2, %0;" : "+l"(d) : "l"(a), "l"(b));
}
__device__ __forceinline__ float2 unpack2(unsigned long long v) {
    float lo, hi;
    asm("mov.b64 {%0, %1}, %2;" : "=f"(lo), "=f"(hi) : "l"(v));
    return make_float2(lo, hi);
}

// ---------------- init: zero logit arrays + active flags, cnt=1 (self loop) ----------------
__global__ void k_init() {
    size_t tid = (size_t)blockIdx.x * blockDim.x + threadIdx.x;
    size_t stride = (size_t)gridDim.x * blockDim.x;
    float4 z = make_float4(0.f, 0.f, 0.f, 0.f);
    float4* pa = reinterpret_cast<float4*>(g_als1);
    float4* pb = reinterpret_cast<float4*>(g_ald1);
    for (size_t i = tid; i < (size_t)NNODE * 2 / 4; i += stride) { pa[i] = z; pb[i] = z; }
    for (size_t i = tid; i < NNODE; i += stride) { g_cnt[i] = 1; g_active[i] = 0; }
}

// ---------------- generic M x 64 GEMM (out = A @ W [+ bias]), f32x2 inner ----------------
// MODE 0: cemb = content @ cp_w + cp_b
// MODE 1: xw2  = g_x(h1) @ w2 ; fused epilogue writes als2/ald2 per row
template <int KDIM, int M, int LDA, int MODE>
__global__ void k_gemm64(const float* __restrict__ Aparam,
                         const float* __restrict__ W,
                         const float* __restrict__ bias,
                         const float* __restrict__ asrc,
                         const float* __restrict__ adst) {
    __shared__ float As[16][128];
    __shared__ float Bs[16][64];
    const float* A = (MODE == 1) ? g_x : Aparam;
    float* out = (MODE == 1) ? g_xw2 : g_cemb;

    int t = threadIdx.x;                 // 256 threads
    int rbase = blockIdx.x * 128;
    int ct = t & 15;                     // 16 col-threads * 4 cols = 64
    int rt = t >> 4;                     // 16 row-threads * 8 rows = 128
    unsigned long long acc2[4][4];       // row-pairs (2p,2p+1) x 4 cols
#pragma unroll
    for (int p = 0; p < 4; p++)
#pragma unroll
        for (int j = 0; j < 4; j++) acc2[p][j] = 0ull;

    for (int kb = 0; kb < KDIM; kb += 16) {
#pragma unroll
        for (int rep = 0; rep < 2; rep++) {
            int idx = t + 256 * rep;     // 512 float4
            int row = idx >> 2, kq = idx & 3;
            int r = rbase + row;
            float4 v = make_float4(0.f, 0.f, 0.f, 0.f);
            if (r < M) v = *reinterpret_cast<const float4*>(&A[(size_t)r * LDA + kb + kq * 4]);
            As[kq * 4 + 0][row] = v.x;
            As[kq * 4 + 1][row] = v.y;
            As[kq * 4 + 2][row] = v.z;
            As[kq * 4 + 3][row] = v.w;
        }
        {
            int kk = t >> 4, col = (t & 15) * 4;
            *reinterpret_cast<float4*>(&Bs[kk][col]) =
                *reinterpret_cast<const float4*>(&W[(size_t)(kb + kk) * 64 + col]);
        }
        __syncthreads();
#pragma unroll
        for (int k = 0; k < 16; k++) {
            float4 a0 = *reinterpret_cast<float4*>(&As[k][rt * 8]);
            float4 a1 = *reinterpret_cast<float4*>(&As[k][rt * 8 + 4]);
            float4 b = *reinterpret_cast<float4*>(&Bs[k][ct * 4]);
            unsigned long long a2[4];
            a2[0] = pack2(a0.x, a0.y);
            a2[1] = pack2(a0.z, a0.w);
            a2[2] = pack2(a1.x, a1.y);
            a2[3] = pack2(a1.z, a1.w);
            unsigned long long bx = pack2(b.x, b.x);
            unsigned long long by = pack2(b.y, b.y);
            unsigned long long bz = pack2(b.z, b.z);
            unsigned long long bw = pack2(b.w, b.w);
#pragma unroll
            for (int p = 0; p < 4; p++) {
                fma2(acc2[p][0], a2[p], bx);
                fma2(acc2[p][1], a2[p], by);
                fma2(acc2[p][2], a2[p], bz);
                fma2(acc2[p][3], a2[p], bw);
            }
        }
        __syncthreads();
    }
    // unpack rows
    float accf[8][4];
#pragma unroll
    for (int p = 0; p < 4; p++)
#pragma unroll
        for (int j = 0; j < 4; j++) {
            float2 v = unpack2(acc2[p][j]);
            accf[2 * p][j] = v.x;
            accf[2 * p + 1][j] = v.y;
        }
#pragma unroll
    for (int i = 0; i < 8; i++) {
        int r = rbase + rt * 8 + i;
        if (r < M) {
            float4 v = make_float4(accf[i][0], accf[i][1], accf[i][2], accf[i][3]);
            if (MODE == 0) {
                v.x += bias[ct * 4 + 0];
                v.y += bias[ct * 4 + 1];
                v.z += bias[ct * 4 + 2];
                v.w += bias[ct * 4 + 3];
            }
            *reinterpret_cast<float4*>(&out[(size_t)r * 64 + ct * 4]) = v;
        }
    }
    if (MODE == 1) {
        // fused al2: per-row dot with asrc2/adst2 ([64] flat), 16-lane reduce
        int lane = t & 31;
        float4 asv = *reinterpret_cast<const float4*>(&asrc[ct * 4]);
        float4 adv = *reinterpret_cast<const float4*>(&adst[ct * 4]);
#pragma unroll
        for (int i = 0; i < 8; i++) {
            float ps = accf[i][0] * asv.x + accf[i][1] * asv.y + accf[i][2] * asv.z + accf[i][3] * asv.w;
            float pd = accf[i][0] * adv.x + accf[i][1] * adv.y + accf[i][2] * adv.z + accf[i][3] * adv.w;
            ps = half16Sum(ps);
            pd = half16Sum(pd);
            int r = rbase + rt * 8 + i;
            if ((lane & 15) == 0 && r < M) { g_als2[r] = ps; g_ald2[r] = pd; }
        }
    }
}

// ---------------- scatter embeddings into node features (+ active flags) ----------------
__global__ void k_scatter(const int* __restrict__ uids, const int* __restrict__ iids,
                          const float* __restrict__ uemb, const float* __restrict__ iemb) {
    int b = blockIdx.x;
    int j = threadIdx.x;  // 64
    int uid = uids[b];
    int iid = iids[b];
    g_x[(size_t)uid * 128 + j] = uemb[(size_t)uid * 64 + j];
    g_x[(size_t)uid * 128 + 64 + j] = 0.f;
    g_x[(size_t)(NUU + iid) * 128 + j] = iemb[(size_t)iid * 64 + j];
    g_x[(size_t)(NUU + iid) * 128 + 64 + j] = g_cemb[(size_t)b * 64 + j];
    if (j == 0) { g_active[uid] = 1; g_active[NUU + iid] = 1; }
}

// ---------------- CSR build ----------------
__global__ void k_hist(const int* __restrict__ ei) {
    int stride = gridDim.x * blockDim.x;
    for (int e = blockIdx.x * blockDim.x + threadIdx.x; e < EE; e += stride)
        atomicAdd(&g_cnt[ei[EE + e]], 1);
}

__global__ void k_scanA() {
    __shared__ int sm[1024];
    int t = threadIdx.x;
    int i = blockIdx.x * 1024 + t;
    int v = (i < NNODE) ? g_cnt[i] : 0;
    sm[t] = v;
    __syncthreads();
    for (int o = 1; o < 1024; o <<= 1) {
        int x = (t >= o) ? sm[t - o] : 0;
        __syncthreads();
        sm[t] += x;
        __syncthreads();
    }
    if (i < NNODE) g_rowptr[i] = sm[t] - v;
    if (t == 1023) g_bsum[blockIdx.x] = sm[1023];
}

__global__ void k_scanB() {
    __shared__ int sm[256];
    int t = threadIdx.x;
    int v = (t < NBLK) ? g_bsum[t] : 0;
    sm[t] = v;
    __syncthreads();
    for (int o = 1; o < 256; o <<= 1) {
        int x = (t >= o) ? sm[t - o] : 0;
        __syncthreads();
        sm[t] += x;
        __syncthreads();
    }
    g_bsumx[t] = sm[t] - v;
}

__global__ void k_scanC() {
    int t = threadIdx.x;
    int i = blockIdx.x * 1024 + t;
    if (i < NNODE) {
        int r = g_rowptr[i] + g_bsumx[blockIdx.x];
        g_rowptr[i] = r;
        g_woff[i] = r;
    }
    if (i == 0) g_rowptr[NNODE] = ETOT;
}

// fill CSR; tag each entry with src-activity in bit 30 (single atomic per edge)
__global__ void k_fill(const int* __restrict__ ei) {
    int stride = gridDim.x * blockDim.x;
    for (int i = blockIdx.x * blockDim.x + threadIdx.x; i < ETOT; i += stride) {
        int s, d;
        if (i < EE) { s = ei[i]; d = ei[EE + i]; }
        else { s = d = i - EE; }
        int pos = atomicAdd(&g_woff[d], 1);
        g_srcs[pos] = s | (g_active[s] ? ACTBIT : 0);
    }
}

// ---------------- layer-1 GEMM over the 2B active rows (gather/scatter), f32x2 inner ----------------
__global__ void k_gemm1(const float* __restrict__ W,  // w1 [128,128]
                        const int* __restrict__ uids, const int* __restrict__ iids) {
    __shared__ float As[16][64];
    __shared__ float Bs[16][128];
    __shared__ int nodes[64];
    int t = threadIdx.x;                 // 256
    int rbase = blockIdx.x * 64;
    if (t < 64) {
        int r = rbase + t;
        nodes[t] = (r < BB) ? uids[r] : (NUU + iids[r - BB]);
    }
    __syncthreads();
    int ct = t & 31;                     // 32 col-threads * 4 cols = 128
    int rt = t >> 5;                     // 8 row-threads * 8 rows = 64
    unsigned long long acc2[4][4];
#pragma unroll
    for (int p = 0; p < 4; p++)
#pragma unroll
        for (int j = 0; j < 4; j++) acc2[p][j] = 0ull;

    for (int kb = 0; kb < 128; kb += 16) {
        {
            int row = t >> 2, kq = t & 3;
            float4 v = *reinterpret_cast<const float4*>(
                &g_x[(size_t)nodes[row] * 128 + kb + kq * 4]);
            As[kq * 4 + 0][row] = v.x;
            As[kq * 4 + 1][row] = v.y;
            As[kq * 4 + 2][row] = v.z;
            As[kq * 4 + 3][row] = v.w;
        }
        {
            int off = t * 8;
            int kk = off >> 7, col = off & 127;
            const float4* p = reinterpret_cast<const float4*>(&W[(size_t)(kb + kk) * 128 + col]);
            *reinterpret_cast<float4*>(&Bs[kk][col]) = p[0];
            *reinterpret_cast<float4*>(&Bs[kk][col + 4]) = p[1];
        }
        __syncthreads();
#pragma unroll
        for (int k = 0; k < 16; k++) {
            float4 a0 = *reinterpret_cast<float4*>(&As[k][rt * 8]);
            float4 a1 = *reinterpret_cast<float4*>(&As[k][rt * 8 + 4]);
            float4 b = *reinterpret_cast<float4*>(&Bs[k][ct * 4]);
            unsigned long long a2[4];
            a2[0] = pack2(a0.x, a0.y);
            a2[1] = pack2(a0.z, a0.w);
            a2[2] = pack2(a1.x, a1.y);
            a2[3] = pack2(a1.z, a1.w);
            unsigned long long bx = pack2(b.x, b.x);
            unsigned long long by = pack2(b.y, b.y);
            unsigned long long bz = pack2(b.z, b.z);
            unsigned long long bw = pack2(b.w, b.w);
#pragma unroll
            for (int p = 0; p < 4; p++) {
                fma2(acc2[p][0], a2[p], bx);
                fma2(acc2[p][1], a2[p], by);
                fma2(acc2[p][2], a2[p], bz);
                fma2(acc2[p][3], a2[p], bw);
            }
        }
        __syncthreads();
    }
#pragma unroll
    for (int p = 0; p < 4; p++) {
        float2 c0 = unpack2(acc2[p][0]);
        float2 c1 = unpack2(acc2[p][1]);
        float2 c2 = unpack2(acc2[p][2]);
        float2 c3 = unpack2(acc2[p][3]);
        int rowA = rt * 8 + 2 * p;
        float4 vA = make_float4(c0.x, c1.x, c2.x, c3.x);
        float4 vB = make_float4(c0.y, c1.y, c2.y, c3.y);
        *reinterpret_cast<float4*>(&g_xw1[(size_t)nodes[rowA] * 128 + ct * 4]) = vA;
        *reinterpret_cast<float4*>(&g_xw1[(size_t)nodes[rowA + 1] * 128 + ct * 4]) = vB;
    }
}

// ---------------- attention logits: layer 1, ACTIVE nodes only ----------------
__global__ void k_al1(const float* __restrict__ asrc, const float* __restrict__ adst,
                      const int* __restrict__ uids, const int* __restrict__ iids) {
    int gt = blockIdx.x * blockDim.x + threadIdx.x;
    int r = gt >> 5, lane = gt & 31;
    if (r >= 2 * BB) return;
    int n = (r < BB) ? uids[r] : (NUU + iids[r - BB]);
    int cg = lane * 4;
    float4 v = *reinterpret_cast<const float4*>(&g_xw1[(size_t)n * 128 + cg]);
    float4 as = *reinterpret_cast<const float4*>(&asrc[cg]);
    float4 ad = *reinterpret_cast<const float4*>(&adst[cg]);
    float ps = v.x * as.x + v.y * as.y + v.z * as.z + v.w * as.w;
    float pd = v.x * ad.x + v.y * ad.y + v.z * ad.z + v.w * ad.w;
#pragma unroll
    for (int o = 8; o > 0; o >>= 1) {
        ps += __shfl_xor_sync(0xffffffffu, ps, o);
        pd += __shfl_xor_sync(0xffffffffu, pd, o);
    }
    if ((lane & 15) == 0) {
        int h = lane >> 4;
        g_als1[(size_t)n * 2 + h] = ps;
        g_ald1[(size_t)n * 2 + h] = pd;
    }
}

// ---------------- layer-1 aggregation (unconditional cached als1 loads,
// ballot-gather over active sources only) ----------------
__global__ void k_agg1(const float* __restrict__ b1) {
    int gt = blockIdx.x * blockDim.x + threadIdx.x;
    int n = gt >> 5, lane = gt & 31;
    if (n >= NNODE) return;
    int beg = g_rowptr[n], end = g_rowptr[n + 1];
    float ad0 = g_ald1[(size_t)n * 2 + 0];
    float ad1 = g_ald1[(size_t)n * 2 + 1];

    int cg = lane * 4;
    bool headHi = (lane >= 16);
    float den0 = 0.f, den1 = 0.f;
    float4 acc = make_float4(0.f, 0.f, 0.f, 0.f);

    for (int c = beg; c < end; c += 32) {
        int i = c + lane;
        bool valid = i < end;
        int sv = valid ? g_srcs[i] : 0;
        int s = sv & SRCMASK;
        float e0 = 0.f, e1 = 0.f;
        if (valid) {
            float2 as = *reinterpret_cast<const float2*>(&g_als1[(size_t)s * 2]);
            e0 = __expf(lrelu02(as.x + ad0));
            e1 = __expf(lrelu02(as.y + ad1));
        }
        den0 += e0;
        den1 += e1;
        unsigned amask = __ballot_sync(0xffffffffu, valid && (sv & ACTBIT));
        while (amask) {
            int j = __ffs(amask) - 1;
            amask &= amask - 1;
            int sj = __shfl_sync(0xffffffffu, s, j);
            float wa = __shfl_sync(0xffffffffu, e0, j);
            float wb = __shfl_sync(0xffffffffu, e1, j);
            float wj = headHi ? wb : wa;
            float4 xv = *reinterpret_cast<const float4*>(&g_xw1[(size_t)sj * 128 + cg]);
            acc.x += wj * xv.x;
            acc.y += wj * xv.y;
            acc.z += wj * xv.z;
            acc.w += wj * xv.w;
        }
    }
    den0 = warpSumAll(den0);
    den1 = warpSumAll(den1);
    float inv = 1.f / ((headHi ? den1 : den0) + 1e-16f);

    float4 bv = *reinterpret_cast<const float4*>(&b1[cg]);
    float4 o;
    o.x = acc.x * inv + bv.x; o.x = o.x > 0.f ? o.x : expm1f(o.x);
    o.y = acc.y * inv + bv.y; o.y = o.y > 0.f ? o.y : expm1f(o.y);
    o.z = acc.z * inv + bv.z; o.z = o.z > 0.f ? o.z : expm1f(o.z);
    o.w = acc.w * inv + bv.w; o.w = o.w > 0.f ? o.w : expm1f(o.w);
    *reinterpret_cast<float4*>(&g_x[(size_t)n * 128 + cg]) = o;  // h1 into g_x
}

// ---------------- layer-2 aggregation: ONLY over the 2B destination nodes the head reads ----------------
__global__ void k_agg2(const float* __restrict__ b2,
                       const int* __restrict__ uids, const int* __restrict__ iids) {
    int gt = blockIdx.x * blockDim.x + threadIdx.x;
    int r = gt >> 5, lane = gt & 31;
    if (r >= 2 * BB) return;
    int n = (r < BB) ? uids[r] : (NUU + iids[r - BB]);
    int beg = g_rowptr[n], end = g_rowptr[n + 1];
    float ad = g_ald2[n];

    int cg = lane * 2;
    float den = 0.f;
    float2 acc = make_float2(0.f, 0.f);
    for (int c = beg; c < end; c += 32) {
        int i = c + lane;
        bool valid = i < end;
        int s = (valid ? g_srcs[i] : 0) & SRCMASK;
        float e = valid ? __expf(lrelu02(g_als2[s] + ad)) : 0.f;
        den += e;
        int cnt = min(32, end - c);
        for (int j = 0; j < cnt; j++) {
            int sj = __shfl_sync(0xffffffffu, s, j);
            float wj = __shfl_sync(0xffffffffu, e, j);
            float2 xv = *reinterpret_cast<const float2*>(&g_xw2[(size_t)sj * 64 + cg]);
            acc.x += wj * xv.x;
            acc.y += wj * xv.y;
        }
    }
    den = warpSumAll(den);
    float inv = 1.f / (den + 1e-16f);
    float2 o = make_float2(acc.x * inv + b2[cg], acc.y * inv + b2[cg + 1]);
    *reinterpret_cast<float2*>(&g_out2[(size_t)n * 64 + cg]) = o;
}

// ---------------- prediction head (warp per batch element) ----------------
__global__ void k_head(const int* __restrict__ uids, const int* __restrict__ iids,
                       const float* __restrict__ uemb,
                       const float* __restrict__ pw1, const float* __restrict__ pb1,
                       const float* __restrict__ pw2, const float* __restrict__ pb2,
                       float* __restrict__ out) {
    __shared__ float cs[8][192];
    int t = threadIdx.x, w = t >> 5, lane = t & 31;
    int b = blockIdx.x * 8 + w;
    int uid = uids[b];
    int iid = iids[b];
    for (int idx = lane; idx < 192; idx += 32) {
        float v;
        if (idx < 64) v = uemb[(size_t)uid * 64 + idx];
        else if (idx < 128) v = g_out2[(size_t)(NUU + iid) * 64 + (idx - 64)];
        else v = g_out2[(size_t)uid * 64 + (idx - 128)];
        cs[w][idx] = v;
    }
    __syncwarp();
    float a0 = pb1[lane], a1 = pb1[lane + 32];
    for (int k = 0; k < 192; k++) {
        float c = cs[w][k];
        a0 += c * pw1[(size_t)k * 64 + lane];
        a1 += c * pw1[(size_t)k * 64 + lane + 32];
    }
    a0 = fmaxf(a0, 0.f);
    a1 = fmaxf(a1, 0.f);
    float p = a0 * pw2[lane] + a1 * pw2[lane + 32];
    p = warpSumAll(p);
    if (lane == 0) out[b] = p + pb2[0];
}

// ---------------- launch: two overlapped chains via capture-legal fork/join ----------------
extern "C" void kernel_launch(void* const* d_in, const int* in_sizes, int n_in,
                              void* d_out, int out_size) {
    const int*   user_ids = (const int*)d_in[0];
    const int*   item_ids = (const int*)d_in[1];
    const float* content  = (const float*)d_in[2];
    const int*   edge_idx = (const int*)d_in[3];
    const float* uemb     = (const float*)d_in[4];
    const float* iemb     = (const float*)d_in[5];
    const float* cp_w     = (const float*)d_in[6];
    const float* cp_b     = (const float*)d_in[7];
    const float* w1       = (const float*)d_in[8];
    const float* asrc1    = (const float*)d_in[9];
    const float* adst1    = (const float*)d_in[10];
    const float* b1       = (const float*)d_in[11];
    const float* w2       = (const float*)d_in[12];
    const float* asrc2    = (const float*)d_in[13];
    const float* adst2    = (const float*)d_in[14];
    const float* b2       = (const float*)d_in[15];
    const float* pw1      = (const float*)d_in[16];
    const float* pb1      = (const float*)d_in[17];
    const float* pw2      = (const float*)d_in[18];
    const float* pb2      = (const float*)d_in[19];
    float* out = (float*)d_out;

    cudaStream_t s2;
    cudaStreamCreateWithFlags(&s2, cudaStreamNonBlocking);
    cudaEvent_t evInit, evScatter, evFeat;
    cudaEventCreateWithFlags(&evInit, cudaEventDisableTiming);
    cudaEventCreateWithFlags(&evScatter, cudaEventDisableTiming);
    cudaEventCreateWithFlags(&evFeat, cudaEventDisableTiming);

    // init on the capturing (legacy) stream, then fork
    k_init<<<1184, 256>>>();
    cudaEventRecord(evInit, 0);
    cudaStreamWaitEvent(s2, evInit, 0);

    // --- feature chain on s2 ---
    k_gemm64<CFD, BB, CFD, 0><<<(BB + 127) / 128, 256, 0, s2>>>(content, cp_w, cp_b, nullptr, nullptr);
    k_scatter<<<BB, 64, 0, s2>>>(user_ids, item_ids, uemb, iemb);
    cudaEventRecord(evScatter, s2);                       // g_active ready
    k_gemm1<<<(2 * BB) / 64, 256, 0, s2>>>(w1, user_ids, item_ids);
    k_al1<<<(2 * BB * 32) / 256, 256, 0, s2>>>(asrc1, adst1, user_ids, item_ids);
    cudaEventRecord(evFeat, s2);                          // join point

    // --- CSR chain on legacy stream (overlaps with feature chain) ---
    k_hist<<<4096, 256>>>(edge_idx);
    k_scanA<<<NBLK, 1024>>>();
    k_scanB<<<1, 256>>>();
    k_scanC<<<NBLK, 1024>>>();
    cudaStreamWaitEvent(0, evScatter, 0);                 // fill needs g_active
    k_fill<<<4096, 256>>>(edge_idx);

    // --- join: aggregation onward on legacy stream ---
    cudaStreamWaitEvent(0, evFeat, 0);
    k_agg1<<<(NNODE * 32) / 256, 256>>>(b1);
    k_gemm64<128, NNODE, 128, 1><<<(NNODE + 127) / 128, 256>>>(nullptr, w2, nullptr, asrc2, adst2);
    k_agg2<<<(2 * BB * 32) / 256, 256>>>(b2, user_ids, item_ids);
    k_head<<<BB / 8, 256>>>(user_ids, item_ids, uemb, pw1, pb1, pw2, pb2, out);
}